// round 14
// baseline (speedup 1.0000x reference)
#include <cuda_runtime.h>

#define BB    16
#define NN    16384
#define NFPS  512
#define NANC  50
#define NREG  50
#define TOPK  4
#define NB    128
#define R2C   0.16f

typedef unsigned int u32;
typedef unsigned long long u64;

__device__ int g_fps_idx[BB][NREG];
__device__ int g_counts[BB][NREG];
__device__ int g_top4[BB][TOPK];

// ---- packed f32x2 helpers (sm_100a) ---------------------------------------
__device__ __forceinline__ u64 pack2(float lo, float hi) {
    u64 r; asm("mov.b64 %0,{%1,%2};" : "=l"(r) : "f"(lo), "f"(hi)); return r;
}
__device__ __forceinline__ void unpack2(u64 v, float& lo, float& hi) {
    asm("mov.b64 {%0,%1},%2;" : "=f"(lo), "=f"(hi) : "l"(v));
}
__device__ __forceinline__ u64 add2(u64 a, u64 b) {
    u64 r; asm("add.rn.f32x2 %0,%1,%2;" : "=l"(r) : "l"(a), "l"(b)); return r;
}
__device__ __forceinline__ u64 mul2(u64 a, u64 b) {
    u64 r; asm("mul.rn.f32x2 %0,%1,%2;" : "=l"(r) : "l"(a), "l"(b)); return r;
}
__device__ __forceinline__ u64 fma2(u64 a, u64 b, u64 c) {
    u64 r; asm("fma.rn.f32x2 %0,%1,%2,%3;" : "=l"(r) : "l"(a), "l"(b), "l"(c)); return r;
}

// ---- cluster / mbarrier helpers --------------------------------------------
__device__ __forceinline__ u32 smem_u32(const void* p) {
    return (u32)__cvta_generic_to_shared(p);
}
__device__ __forceinline__ u32 mapa_rank(u32 addr, u32 rank) {
    u32 r;
    asm("mapa.shared::cluster.u32 %0,%1,%2;" : "=r"(r) : "r"(addr), "r"(rank));
    return r;
}
__device__ __forceinline__ void st_cluster_b64(u32 addr, u64 v) {
    asm volatile("st.shared::cluster.b64 [%0],%1;" :: "r"(addr), "l"(v) : "memory");
}
__device__ __forceinline__ void mbar_init(u32 addr, u32 cnt) {
    asm volatile("mbarrier.init.shared.b64 [%0],%1;" :: "r"(addr), "r"(cnt) : "memory");
}
__device__ __forceinline__ void mbar_arrive_remote(u32 remote_addr) {
    asm volatile("mbarrier.arrive.release.cluster.shared::cluster.b64 _,[%0];"
                 :: "r"(remote_addr) : "memory");
}
__device__ __forceinline__ void mbar_wait(u32 addr, u32 parity) {
    asm volatile(
        "{\n\t.reg .pred P;\n\t"
        "WL_%=:\n\t"
        "mbarrier.try_wait.parity.acquire.cluster.shared::cta.b64 P,[%0],%1,0x989680;\n\t"
        "@P bra.uni WD_%=;\n\t"
        "bra.uni WL_%=;\n\t"
        "WD_%=:\n\t}"
        :: "r"(addr), "r"(parity) : "memory");
}
#define CLUSTER_SYNC() do {                                          \
    asm volatile("barrier.cluster.arrive.aligned;" ::: "memory");    \
    asm volatile("barrier.cluster.wait.aligned;" ::: "memory");      \
} while (0)

// ============================================================================
// FPS, cluster of 2 CTAs per batch; 1024 threads x 8 points (4 packed
// pairs, register-resident) + FULL 16K point cache in smem (keys alone
// identify candidates globally).  Structure = validated R13: finish dist
// update with committed centroid (2 pending pairs after a spec hit, 4
// after a miss); R9 reduction (redux -> bar1 -> flat 32-warp max ->
// atomicMin(global idx) -> bar2); t0 ships the 8-byte key to the peer's
// parity slot + remote mbar arrive (count=1); all threads read the local
// candidate's coords from the cache and speculatively update pairs 0-1
// into sd[] (dist untouched); mbar wait; key compare -> commit or discard.
// fmin only ever applied with the true selected centroid; key order ==
// (dist, lowest index) == jnp.argmax.  Bit-exact.
// ============================================================================
#define CSZ   2
#define LPTS  (NN / CSZ)     /* 8192 */
#define FT    1024
#define NWP   (FT / 32)      /* 32 */
#define FPPT  (LPTS / FT)    /* 8 -> 4 packed pairs */

#define FPS_SMEM (3 * NN * (int)sizeof(float))

template<int NIT, bool MAIN>
__global__ void __launch_bounds__(FT, 1) __cluster_dims__(CSZ, 1, 1)
fps_kernel(const float* __restrict__ pts, float* __restrict__ out)
{
    extern __shared__ float sh[];
    float* SX = sh;
    float* SY = sh + NN;
    float* SZ = sh + 2 * NN;
    __shared__ __align__(16) u32 s_wmax[NWP];
    __shared__ int s_widx[2];
    __shared__ __align__(8) u64 s_pslot[2];   // [parity]: peer's key
    __shared__ __align__(8) u64 s_mbar[1];
    __shared__ float4 s_hist[NIT];

    const int rank = blockIdx.x, b = blockIdx.y, t = threadIdx.x;
    const int lane = t & 31, warp = t >> 5;
    const float* base = pts + (size_t)b * 3 * NN;
    const int g0 = rank * LPTS;
    const u32 peer = (u32)(rank ^ 1);
    const u32 mbar_a = smem_u32(&s_mbar[0]);

    if (t == 0) {
        s_widx[0] = 0x7fffffff;
        s_widx[1] = 0x7fffffff;
        mbar_init(mbar_a, 1);
    }
    // full point cache (both halves)
    for (int n = t; n < NN; n += FT) {
        SX[n] = base[n];
        SY[n] = base[NN + n];
        SZ[n] = base[2 * NN + n];
    }
    __syncthreads();
    CLUSTER_SYNC();   // peer mbar init visible before any remote arrive

    // my 8 points in registers, packed pairs (slots 2j, 2j+1)
    u64 rx[4], ry[4], rz[4];
#pragma unroll
    for (int j = 0; j < 4; j++) {
        const int n0 = g0 + t + (2 * j) * FT, n1 = n0 + FT;
        rx[j] = pack2(SX[n0], SX[n1]);
        ry[j] = pack2(SY[n0], SY[n1]);
        rz[j] = pack2(SZ[n0], SZ[n1]);
    }
    float dist[FPPT];
#pragma unroll
    for (int k = 0; k < FPPT; k++) dist[k] = 1e10f;

    float cx = SX[0], cy = SY[0], cz = SZ[0];   // first centroid: point 0
    int cur = 0;
    bool hit = false;
    float sv0 = -1.0f, sv1 = -1.0f;
    float sd[4];

#define PAIR_UPD(J, NX, NY, NZ, DA, DB, VA, VB) {                            \
        u64 dx = add2(rx[J], NX), dy = add2(ry[J], NY), dz = add2(rz[J], NZ);\
        u64 s = mul2(dx, dx); s = fma2(dy, dy, s); s = fma2(dz, dz, s);      \
        float a_, c_; unpack2(s, a_, c_);                                    \
        DA = fminf(dist[2 * (J)], a_); DB = fminf(dist[2 * (J) + 1], c_);    \
        VA = fmaxf(VA, DA); VB = fmaxf(VB, DB); }

    for (int i = 0; i < NIT; i++) {
        const int par = i & 1;
        if (rank == 0 && t == 0)
            s_hist[i] = make_float4(cx, cy, cz, __int_as_float(cur));

        // ---- finish dist update with the committed centroid ----
        const u64 nx = pack2(-cx, -cx), ny = pack2(-cy, -cy), nz = pack2(-cz, -cz);
        float v0, v1;
        if (hit) {                 // pairs 0-1 already committed from spec
            v0 = sv0; v1 = sv1;
#pragma unroll
            for (int j = 2; j < 4; j++) {
                float d0, d1;
                PAIR_UPD(j, nx, ny, nz, d0, d1, v0, v1)
                dist[2 * j] = d0; dist[2 * j + 1] = d1;
            }
        } else {
            v0 = -1.0f; v1 = -1.0f;
#pragma unroll
            for (int j = 0; j < 4; j++) {
                float d0, d1;
                PAIR_UPD(j, nx, ny, nz, d0, d1, v0, v1)
                dist[2 * j] = d0; dist[2 * j + 1] = d1;
            }
        }
        const float vmax = fmaxf(v0, v1);

        // ---- R9 reduction ----
        const u32 wm = __reduce_max_sync(0xffffffffu, __float_as_uint(vmax));
        if (lane == 0) s_wmax[warp] = wm;
        __syncthreads();                             // bar1
        if (t == 0) s_widx[par ^ 1] = 0x7fffffff;

        u32 m;
        {
            const uint4* p4 = (const uint4*)s_wmax;
            uint4 q = p4[0];
            m = max(max(q.x, q.y), max(q.z, q.w));
#pragma unroll
            for (int w = 1; w < NWP / 4; w++) {
                q = p4[w];
                m = max(m, max(max(q.x, q.y), max(q.z, q.w)));
            }
        }

        if (__float_as_uint(vmax) == m) {
#pragma unroll
            for (int k = 0; k < FPPT; k++)
                if (__float_as_uint(dist[k]) == m)
                    atomicMin(&s_widx[par], g0 + t + k * FT);
        }
        __syncthreads();                             // bar2
        const int widx = s_widx[par];
        const u64 lkey = ((u64)m << 14) | (u64)(16383u - (u32)widx);

        // ---- t0 ships the key to the peer (8 bytes + 1 arrive) ----
        if (t == 0) {
            st_cluster_b64(mapa_rank(smem_u32(&s_pslot[par]), peer), lkey);
            mbar_arrive_remote(mapa_rank(mbar_a, peer));
        }

        // ---- local candidate coords from the cache (broadcast LDS) ----
        const float lcx = SX[widx], lcy = SY[widx], lcz = SZ[widx];
        const u64 lnx = pack2(-lcx, -lcx);
        const u64 lny = pack2(-lcy, -lcy);
        const u64 lnz = pack2(-lcz, -lcz);

        // ---- speculative update of pairs 0-1 (fills the transit window) ----
        sv0 = -1.0f; sv1 = -1.0f;
#pragma unroll
        for (int j = 0; j < 2; j++) {
            PAIR_UPD(j, lnx, lny, lnz, sd[2 * j], sd[2 * j + 1], sv0, sv1)
        }

        // ---- peer candidate ----
        mbar_wait(mbar_a, (u32)par);
        const u64 pkey = s_pslot[par];

        if (lkey >= pkey) {        // local candidate is the global winner
            hit = true;
#pragma unroll
            for (int k = 0; k < 4; k++) dist[k] = sd[k];
            cx = lcx; cy = lcy; cz = lcz;
            cur = widx;
        } else {                   // peer won: discard spec
            hit = false;
            const int pw = 16383 - (int)(pkey & 0x3FFFu);
            cx = SX[pw]; cy = SY[pw]; cz = SZ[pw];
            cur = pw;
        }
    }
#undef PAIR_UPD

    if (rank == 0) {
        __syncthreads();
        if (MAIN) {
            if (t < NIT) {
                const float4 h = s_hist[t];
                float* o = out + ((size_t)b * 1536 + 1024 + t) * 3;
                o[0] = h.x; o[1] = h.y; o[2] = h.z;
            }
        } else {
            if (t < NIT)
                g_fps_idx[b][t] = __float_as_int(s_hist[t].w);
        }
    }
    CLUSTER_SYNC();   // no CTA exits while peer stores may be in flight
}

// ============================================================================
// Kernel 2: per-(batch, anchor) ball count.  grid = (NREG, BB)
// ============================================================================
__global__ void count_kernel(const float* __restrict__ pts)
{
    const int a = blockIdx.x, b = blockIdx.y;
    const int t = threadIdx.x;
    const float* base = pts + (size_t)b * 3 * NN;
    const int aidx = g_fps_idx[b][a];
    const float ax = base[aidx], ay = base[NN + aidx], az = base[2 * NN + aidx];
    const float a2 = ax * ax + ay * ay + az * az;

    int cnt = 0;
    for (int n = t; n < NN; n += 256) {
        float x = base[n], y = base[NN + n], z = base[2 * NN + n];
        float dot = ax * x + ay * y + az * z;
        float p2 = x * x + y * y + z * z;
        float d = (-2.0f * dot + a2) + p2;
        cnt += (d < R2C) ? 1 : 0;
    }
    __shared__ int s_c[8];
#pragma unroll
    for (int o = 16; o > 0; o >>= 1) cnt += __shfl_xor_sync(0xffffffffu, cnt, o);
    if ((t & 31) == 0) s_c[t >> 5] = cnt;
    __syncthreads();
    if (t == 0) {
        int s = 0;
#pragma unroll
        for (int w = 0; w < 8; w++) s += s_c[w];
        g_counts[b][a] = min(s, 1000);
    }
}

// ============================================================================
// Kernel 3: top-4 anchors by count (ties -> lower index).  grid = BB
// ============================================================================
__global__ void top4_kernel()
{
    const int b = blockIdx.x;
    if (threadIdx.x != 0) return;
    int cnts[NREG];
    for (int a = 0; a < NREG; a++) cnts[a] = g_counts[b][a];
    for (int j = 0; j < TOPK; j++) {
        int best = -1, bi = 0;
        for (int a = 0; a < NREG; a++)
            if (cnts[a] > best) { best = cnts[a]; bi = a; }
        g_top4[b][j] = g_fps_idx[b][bi];
        cnts[bi] = -2;
    }
}

// ============================================================================
// Kernel 4: 128-NN per (query, batch).  grid = (TOPK, BB)  (validated, 54us;
// runs on the hidden side stream, off the critical path)
// ============================================================================
#define KT   512
#define KPPT 32

__global__ void __launch_bounds__(KT, 1)
knn_kernel(const float* __restrict__ pts, float* __restrict__ out)
{
    const int q = blockIdx.x, b = blockIdx.y;
    const int t = threadIdx.x, lane = t & 31, warp = t >> 5;
    const float* base = pts + (size_t)b * 3 * NN;
    __shared__ u32 s_wmin[KT / 32];
    __shared__ u32 s_minv;
    __shared__ int s_tid[2];
    __shared__ int s_win[NB];

    if (t == 0) { s_tid[0] = 0x7fffffff; s_tid[1] = 0x7fffffff; }

    const int qidx = g_top4[b][q];
    const float qx = base[qidx], qy = base[NN + qidx], qz = base[2 * NN + qidx];
    const float q2 = qx * qx + qy * qy + qz * qz;

    const int p0 = t * KPPT;
    u32 u[KPPT];

#define DPT(X, Y, Z, K) {                                                   \
        float dot = qx * (X) + qy * (Y) + qz * (Z);                         \
        float p2 = (X) * (X) + (Y) * (Y) + (Z) * (Z);                       \
        float d = (-2.0f * dot + q2) + p2;                                  \
        u32 ub = __float_as_uint(d);                                        \
        ub = (ub & 0x80000000u) ? ~ub : (ub | 0x80000000u);                 \
        u[K] = ub; }

#pragma unroll
    for (int g = 0; g < 8; g++) {
        const float4 x4 = *(const float4*)&base[p0 + 4 * g];
        const float4 y4 = *(const float4*)&base[NN + p0 + 4 * g];
        const float4 z4 = *(const float4*)&base[2 * NN + p0 + 4 * g];
        DPT(x4.x, y4.x, z4.x, 4 * g + 0)
        DPT(x4.y, y4.y, z4.y, 4 * g + 1)
        DPT(x4.z, y4.z, z4.z, 4 * g + 2)
        DPT(x4.w, y4.w, z4.w, 4 * g + 3)
    }
#undef DPT

    u32 gmin[4];
#pragma unroll
    for (int g = 0; g < 4; g++) {
        u32 m = u[8 * g];
#pragma unroll
        for (int k = 1; k < 8; k++) m = min(m, u[8 * g + k]);
        gmin[g] = m;
    }
    u32 tmin = min(min(gmin[0], gmin[1]), min(gmin[2], gmin[3]));
    __syncthreads();

    for (int j = 0; j < NB; j++) {
        u32 wm = __reduce_min_sync(0xffffffffu, tmin);
        if (lane == 0) s_wmin[warp] = wm;
        __syncthreads();
        if (warp == 0) {
            u32 v = (lane < KT / 32) ? s_wmin[lane] : 0xffffffffu;
            v = __reduce_min_sync(0xffffffffu, v);
            if (lane == 0) s_minv = v;
        }
        __syncthreads();
        const u32 m = s_minv;
        const int slot = j & 1;
        if (tmin == m) atomicMin(&s_tid[slot], t);
        if (t == 0) s_tid[slot ^ 1] = 0x7fffffff;
        __syncthreads();
        if (t == s_tid[slot]) {
            bool found = false;
#pragma unroll
            for (int g = 0; g < 4; g++) {
                if (!found && gmin[g] == m) {
                    bool f2 = false;
#pragma unroll
                    for (int k = 0; k < 8; k++) {
                        if (!f2 && u[8 * g + k] == m) {
                            u[8 * g + k] = 0xffffffffu;
                            s_win[j] = p0 + 8 * g + k;
                            f2 = true;
                        }
                    }
                    u32 nm = u[8 * g];
#pragma unroll
                    for (int k = 1; k < 8; k++) nm = min(nm, u[8 * g + k]);
                    gmin[g] = nm;
                    found = true;
                }
            }
            tmin = min(min(gmin[0], gmin[1]), min(gmin[2], gmin[3]));
        }
    }

    __syncthreads();
    if (t < NB) {
        const int win = s_win[t];
        const float x = base[win], y = base[NN + win], z = base[2 * NN + win];
        const size_t r = (size_t)b * 1536 + (size_t)q * NB + t;
        float* o1 = out + r * 3;
        o1[0] = x; o1[1] = y; o1[2] = z;
        float* o2 = out + (r + 512) * 3;
        o2[0] = x; o2[1] = y; o2[2] = z;
    }
}

// ============================================================================
// Launch: side stream runs the anchor pipeline (fps50 -> count -> top4 ->
// knn) overlapped with the full 512-iteration FPS on the main stream.
// Disjoint out regions; no shared state.  Streams/events created fresh per
// call (host-side objects only; not destroyed to keep the capture valid).
// ============================================================================
extern "C" void kernel_launch(void* const* d_in, const int* in_sizes, int n_in,
                              void* d_out, int out_size)
{
    const float* pts = (const float*)d_in[0];
    float* out = (float*)d_out;

    cudaFuncSetAttribute(fps_kernel<NANC, false>,
                         cudaFuncAttributeMaxDynamicSharedMemorySize, FPS_SMEM);
    cudaFuncSetAttribute(fps_kernel<NFPS, true>,
                         cudaFuncAttributeMaxDynamicSharedMemorySize, FPS_SMEM);

    cudaStream_t s2;
    cudaStreamCreateWithFlags(&s2, cudaStreamNonBlocking);
    cudaEvent_t e1, e2;
    cudaEventCreateWithFlags(&e1, cudaEventDisableTiming);
    cudaEventCreateWithFlags(&e2, cudaEventDisableTiming);

    cudaEventRecord(e1, 0);             // fork
    cudaStreamWaitEvent(s2, e1, 0);

    fps_kernel<NANC, false><<<dim3(CSZ, BB), FT, FPS_SMEM, s2>>>(pts, out);
    count_kernel<<<dim3(NREG, BB), 256, 0, s2>>>(pts);
    top4_kernel<<<BB, 32, 0, s2>>>();
    knn_kernel<<<dim3(TOPK, BB), KT, 0, s2>>>(pts, out);
    cudaEventRecord(e2, s2);

    fps_kernel<NFPS, true><<<dim3(CSZ, BB), FT, FPS_SMEM>>>(pts, out);

    cudaStreamWaitEvent(0, e2, 0);      // join
}

// round 15
// speedup vs baseline: 1.1429x; 1.1429x over previous
#include <cuda_runtime.h>

#define BB    16
#define NN    16384
#define NFPS  512
#define NANC  50
#define NREG  50
#define TOPK  4
#define NB    128
#define R2C   0.16f

typedef unsigned int u32;
typedef unsigned long long u64;

__device__ int g_fps_idx[BB][NREG];
__device__ int g_counts[BB][NREG];
__device__ int g_top4[BB][TOPK];

// ---- packed f32x2 helpers (sm_100a) ---------------------------------------
__device__ __forceinline__ u64 pack2(float lo, float hi) {
    u64 r; asm("mov.b64 %0,{%1,%2};" : "=l"(r) : "f"(lo), "f"(hi)); return r;
}
__device__ __forceinline__ void unpack2(u64 v, float& lo, float& hi) {
    asm("mov.b64 {%0,%1},%2;" : "=f"(lo), "=f"(hi) : "l"(v));
}
__device__ __forceinline__ u64 add2(u64 a, u64 b) {
    u64 r; asm("add.rn.f32x2 %0,%1,%2;" : "=l"(r) : "l"(a), "l"(b)); return r;
}
__device__ __forceinline__ u64 mul2(u64 a, u64 b) {
    u64 r; asm("mul.rn.f32x2 %0,%1,%2;" : "=l"(r) : "l"(a), "l"(b)); return r;
}
__device__ __forceinline__ u64 fma2(u64 a, u64 b, u64 c) {
    u64 r; asm("fma.rn.f32x2 %0,%1,%2,%3;" : "=l"(r) : "l"(a), "l"(b), "l"(c)); return r;
}

// ---- cluster / mbarrier helpers --------------------------------------------
__device__ __forceinline__ u32 smem_u32(const void* p) {
    return (u32)__cvta_generic_to_shared(p);
}
__device__ __forceinline__ u32 mapa_rank(u32 addr, u32 rank) {
    u32 r;
    asm("mapa.shared::cluster.u32 %0,%1,%2;" : "=r"(r) : "r"(addr), "r"(rank));
    return r;
}
__device__ __forceinline__ void st_cluster_b64(u32 addr, u64 v) {
    asm volatile("st.shared::cluster.b64 [%0],%1;" :: "r"(addr), "l"(v) : "memory");
}
__device__ __forceinline__ void mbar_init(u32 addr, u32 cnt) {
    asm volatile("mbarrier.init.shared.b64 [%0],%1;" :: "r"(addr), "r"(cnt) : "memory");
}
__device__ __forceinline__ void mbar_arrive_remote(u32 remote_addr) {
    asm volatile("mbarrier.arrive.release.cluster.shared::cluster.b64 _,[%0];"
                 :: "r"(remote_addr) : "memory");
}
__device__ __forceinline__ void mbar_wait(u32 addr, u32 parity) {
    asm volatile(
        "{\n\t.reg .pred P;\n\t"
        "WL_%=:\n\t"
        "mbarrier.try_wait.parity.acquire.cluster.shared::cta.b64 P,[%0],%1,0x989680;\n\t"
        "@P bra.uni WD_%=;\n\t"
        "bra.uni WL_%=;\n\t"
        "WD_%=:\n\t}"
        :: "r"(addr), "r"(parity) : "memory");
}
#define CLUSTER_SYNC() do {                                          \
    asm volatile("barrier.cluster.arrive.aligned;" ::: "memory");    \
    asm volatile("barrier.cluster.wait.aligned;" ::: "memory");      \
} while (0)

// ============================================================================
// FPS, cluster of 2 CTAs per batch; 512 threads x 16 points (8 packed
// pairs, register-resident) + FULL 16K point cache in smem (keys alone
// identify candidates globally).  Validated R13 structure with tuned
// speculation depth S=3: finish dist update with the committed centroid
// (5 pending pairs after a spec hit, 8 after a miss); R9 reduction
// (redux -> bar1 -> flat max -> atomicMin(global idx) -> bar2); t0 ships
// the 8-byte key to the peer's parity slot + remote mbar arrive (count=1);
// all threads read the local candidate's coords from the cache and
// speculatively update pairs 0-2 into sd[] (dist untouched; spec length
// ~= DSMEM transit window); mbar wait; key compare -> commit or discard.
// fmin only ever applied with the true selected centroid; key order ==
// (dist, lowest index) == jnp.argmax.  Bit-exact.
// ============================================================================
#define CSZ   2
#define LPTS  (NN / CSZ)     /* 8192 */
#define FT    512
#define FPPT  (LPTS / FT)    /* 16 -> 8 packed pairs */
#define SPEC  3              /* speculated pairs (tuned: covers transit) */

#define FPS_SMEM (3 * NN * (int)sizeof(float))

template<int NIT, bool MAIN>
__global__ void __launch_bounds__(FT, 1) __cluster_dims__(CSZ, 1, 1)
fps_kernel(const float* __restrict__ pts, float* __restrict__ out)
{
    extern __shared__ float sh[];
    float* SX = sh;
    float* SY = sh + NN;
    float* SZ = sh + 2 * NN;
    __shared__ __align__(16) u32 s_wmax[16];
    __shared__ int s_widx[2];
    __shared__ __align__(8) u64 s_pslot[2];   // [parity]: peer's key
    __shared__ __align__(8) u64 s_mbar[1];
    __shared__ float4 s_hist[NIT];

    const int rank = blockIdx.x, b = blockIdx.y, t = threadIdx.x;
    const int lane = t & 31, warp = t >> 5;
    const float* base = pts + (size_t)b * 3 * NN;
    const int g0 = rank * LPTS;
    const u32 peer = (u32)(rank ^ 1);
    const u32 mbar_a = smem_u32(&s_mbar[0]);

    if (t == 0) {
        s_widx[0] = 0x7fffffff;
        s_widx[1] = 0x7fffffff;
        mbar_init(mbar_a, 1);
    }
    // full point cache (both halves)
    for (int n = t; n < NN; n += FT) {
        SX[n] = base[n];
        SY[n] = base[NN + n];
        SZ[n] = base[2 * NN + n];
    }
    __syncthreads();
    CLUSTER_SYNC();   // peer mbar init visible before any remote arrive

    // my 8192 points in registers, packed pairs (slots 2j, 2j+1)
    u64 rx[8], ry[8], rz[8];
#pragma unroll
    for (int j = 0; j < 8; j++) {
        const int n0 = g0 + t + (2 * j) * FT, n1 = n0 + FT;
        rx[j] = pack2(SX[n0], SX[n1]);
        ry[j] = pack2(SY[n0], SY[n1]);
        rz[j] = pack2(SZ[n0], SZ[n1]);
    }
    float dist[FPPT];
#pragma unroll
    for (int k = 0; k < FPPT; k++) dist[k] = 1e10f;

    float cx = SX[0], cy = SY[0], cz = SZ[0];   // first centroid: point 0
    int cur = 0;
    bool hit = false;
    float sv0 = -1.0f, sv1 = -1.0f;
    float sd[2 * SPEC];

#define PAIR_UPD(J, NX, NY, NZ, DA, DB, VA, VB) {                            \
        u64 dx = add2(rx[J], NX), dy = add2(ry[J], NY), dz = add2(rz[J], NZ);\
        u64 s = mul2(dx, dx); s = fma2(dy, dy, s); s = fma2(dz, dz, s);      \
        float a_, c_; unpack2(s, a_, c_);                                    \
        DA = fminf(dist[2 * (J)], a_); DB = fminf(dist[2 * (J) + 1], c_);    \
        VA = fmaxf(VA, DA); VB = fmaxf(VB, DB); }

    for (int i = 0; i < NIT; i++) {
        const int par = i & 1;
        if (rank == 0 && t == 0)
            s_hist[i] = make_float4(cx, cy, cz, __int_as_float(cur));

        // ---- finish dist update with the committed centroid ----
        const u64 nx = pack2(-cx, -cx), ny = pack2(-cy, -cy), nz = pack2(-cz, -cz);
        float v0, v1;
        if (hit) {                 // pairs 0..SPEC-1 already committed from spec
            v0 = sv0; v1 = sv1;
#pragma unroll
            for (int j = SPEC; j < 8; j++) {
                float d0, d1;
                PAIR_UPD(j, nx, ny, nz, d0, d1, v0, v1)
                dist[2 * j] = d0; dist[2 * j + 1] = d1;
            }
        } else {
            v0 = -1.0f; v1 = -1.0f;
#pragma unroll
            for (int j = 0; j < 8; j++) {
                float d0, d1;
                PAIR_UPD(j, nx, ny, nz, d0, d1, v0, v1)
                dist[2 * j] = d0; dist[2 * j + 1] = d1;
            }
        }
        const float vmax = fmaxf(v0, v1);

        // ---- R9 reduction (validated) ----
        const u32 wm = __reduce_max_sync(0xffffffffu, __float_as_uint(vmax));
        if (lane == 0) s_wmax[warp] = wm;
        __syncthreads();                             // bar1
        if (t == 0) s_widx[par ^ 1] = 0x7fffffff;

        const uint4 q0 = *(const uint4*)&s_wmax[0];
        const uint4 q1 = *(const uint4*)&s_wmax[4];
        const uint4 q2 = *(const uint4*)&s_wmax[8];
        const uint4 q3 = *(const uint4*)&s_wmax[12];
        u32 m = max(max(max(q0.x, q0.y), max(q0.z, q0.w)),
                    max(max(q1.x, q1.y), max(q1.z, q1.w)));
        m = max(m, max(max(max(q2.x, q2.y), max(q2.z, q2.w)),
                       max(max(q3.x, q3.y), max(q3.z, q3.w))));

        if (__float_as_uint(vmax) == m) {
#pragma unroll
            for (int k = 0; k < FPPT; k++)
                if (__float_as_uint(dist[k]) == m)
                    atomicMin(&s_widx[par], g0 + t + k * FT);
        }
        __syncthreads();                             // bar2
        const int widx = s_widx[par];
        const u64 lkey = ((u64)m << 14) | (u64)(16383u - (u32)widx);

        // ---- t0 ships the key to the peer (8 bytes + 1 arrive) ----
        if (t == 0) {
            st_cluster_b64(mapa_rank(smem_u32(&s_pslot[par]), peer), lkey);
            mbar_arrive_remote(mapa_rank(mbar_a, peer));
        }

        // ---- local candidate coords from the cache (broadcast LDS) ----
        const float lcx = SX[widx], lcy = SY[widx], lcz = SZ[widx];
        const u64 lnx = pack2(-lcx, -lcx);
        const u64 lny = pack2(-lcy, -lcy);
        const u64 lnz = pack2(-lcz, -lcz);

        // ---- speculative update of pairs 0..SPEC-1 (covers transit) ----
        sv0 = -1.0f; sv1 = -1.0f;
#pragma unroll
        for (int j = 0; j < SPEC; j++) {
            PAIR_UPD(j, lnx, lny, lnz, sd[2 * j], sd[2 * j + 1], sv0, sv1)
        }

        // ---- peer candidate ----
        mbar_wait(mbar_a, (u32)par);
        const u64 pkey = s_pslot[par];

        if (lkey >= pkey) {        // local candidate is the global winner
            hit = true;
#pragma unroll
            for (int k = 0; k < 2 * SPEC; k++) dist[k] = sd[k];
            cx = lcx; cy = lcy; cz = lcz;
            cur = widx;
        } else {                   // peer won: discard spec
            hit = false;
            const int pw = 16383 - (int)(pkey & 0x3FFFu);
            cx = SX[pw]; cy = SY[pw]; cz = SZ[pw];
            cur = pw;
        }
    }
#undef PAIR_UPD

    if (rank == 0) {
        __syncthreads();
        if (MAIN) {
            if (t < NIT) {
                const float4 h = s_hist[t];
                float* o = out + ((size_t)b * 1536 + 1024 + t) * 3;
                o[0] = h.x; o[1] = h.y; o[2] = h.z;
            }
        } else {
            if (t < NIT)
                g_fps_idx[b][t] = __float_as_int(s_hist[t].w);
        }
    }
    CLUSTER_SYNC();   // no CTA exits while peer stores may be in flight
}

// ============================================================================
// Kernel 2: per-(batch, anchor) ball count.  grid = (NREG, BB)
// ============================================================================
__global__ void count_kernel(const float* __restrict__ pts)
{
    const int a = blockIdx.x, b = blockIdx.y;
    const int t = threadIdx.x;
    const float* base = pts + (size_t)b * 3 * NN;
    const int aidx = g_fps_idx[b][a];
    const float ax = base[aidx], ay = base[NN + aidx], az = base[2 * NN + aidx];
    const float a2 = ax * ax + ay * ay + az * az;

    int cnt = 0;
    for (int n = t; n < NN; n += 256) {
        float x = base[n], y = base[NN + n], z = base[2 * NN + n];
        float dot = ax * x + ay * y + az * z;
        float p2 = x * x + y * y + z * z;
        float d = (-2.0f * dot + a2) + p2;
        cnt += (d < R2C) ? 1 : 0;
    }
    __shared__ int s_c[8];
#pragma unroll
    for (int o = 16; o > 0; o >>= 1) cnt += __shfl_xor_sync(0xffffffffu, cnt, o);
    if ((t & 31) == 0) s_c[t >> 5] = cnt;
    __syncthreads();
    if (t == 0) {
        int s = 0;
#pragma unroll
        for (int w = 0; w < 8; w++) s += s_c[w];
        g_counts[b][a] = min(s, 1000);
    }
}

// ============================================================================
// Kernel 3: top-4 anchors by count (ties -> lower index).  grid = BB
// ============================================================================
__global__ void top4_kernel()
{
    const int b = blockIdx.x;
    if (threadIdx.x != 0) return;
    int cnts[NREG];
    for (int a = 0; a < NREG; a++) cnts[a] = g_counts[b][a];
    for (int j = 0; j < TOPK; j++) {
        int best = -1, bi = 0;
        for (int a = 0; a < NREG; a++)
            if (cnts[a] > best) { best = cnts[a]; bi = a; }
        g_top4[b][j] = g_fps_idx[b][bi];
        cnts[bi] = -2;
    }
}

// ============================================================================
// Kernel 4: 128-NN per (query, batch).  grid = (TOPK, BB)  (validated, 54us;
// runs on the hidden side stream, off the critical path)
// ============================================================================
#define KT   512
#define KPPT 32

__global__ void __launch_bounds__(KT, 1)
knn_kernel(const float* __restrict__ pts, float* __restrict__ out)
{
    const int q = blockIdx.x, b = blockIdx.y;
    const int t = threadIdx.x, lane = t & 31, warp = t >> 5;
    const float* base = pts + (size_t)b * 3 * NN;
    __shared__ u32 s_wmin[KT / 32];
    __shared__ u32 s_minv;
    __shared__ int s_tid[2];
    __shared__ int s_win[NB];

    if (t == 0) { s_tid[0] = 0x7fffffff; s_tid[1] = 0x7fffffff; }

    const int qidx = g_top4[b][q];
    const float qx = base[qidx], qy = base[NN + qidx], qz = base[2 * NN + qidx];
    const float q2 = qx * qx + qy * qy + qz * qz;

    const int p0 = t * KPPT;
    u32 u[KPPT];

#define DPT(X, Y, Z, K) {                                                   \
        float dot = qx * (X) + qy * (Y) + qz * (Z);                         \
        float p2 = (X) * (X) + (Y) * (Y) + (Z) * (Z);                       \
        float d = (-2.0f * dot + q2) + p2;                                  \
        u32 ub = __float_as_uint(d);                                        \
        ub = (ub & 0x80000000u) ? ~ub : (ub | 0x80000000u);                 \
        u[K] = ub; }

#pragma unroll
    for (int g = 0; g < 8; g++) {
        const float4 x4 = *(const float4*)&base[p0 + 4 * g];
        const float4 y4 = *(const float4*)&base[NN + p0 + 4 * g];
        const float4 z4 = *(const float4*)&base[2 * NN + p0 + 4 * g];
        DPT(x4.x, y4.x, z4.x, 4 * g + 0)
        DPT(x4.y, y4.y, z4.y, 4 * g + 1)
        DPT(x4.z, y4.z, z4.z, 4 * g + 2)
        DPT(x4.w, y4.w, z4.w, 4 * g + 3)
    }
#undef DPT

    u32 gmin[4];
#pragma unroll
    for (int g = 0; g < 4; g++) {
        u32 m = u[8 * g];
#pragma unroll
        for (int k = 1; k < 8; k++) m = min(m, u[8 * g + k]);
        gmin[g] = m;
    }
    u32 tmin = min(min(gmin[0], gmin[1]), min(gmin[2], gmin[3]));
    __syncthreads();

    for (int j = 0; j < NB; j++) {
        u32 wm = __reduce_min_sync(0xffffffffu, tmin);
        if (lane == 0) s_wmin[warp] = wm;
        __syncthreads();
        if (warp == 0) {
            u32 v = (lane < KT / 32) ? s_wmin[lane] : 0xffffffffu;
            v = __reduce_min_sync(0xffffffffu, v);
            if (lane == 0) s_minv = v;
        }
        __syncthreads();
        const u32 m = s_minv;
        const int slot = j & 1;
        if (tmin == m) atomicMin(&s_tid[slot], t);
        if (t == 0) s_tid[slot ^ 1] = 0x7fffffff;
        __syncthreads();
        if (t == s_tid[slot]) {
            bool found = false;
#pragma unroll
            for (int g = 0; g < 4; g++) {
                if (!found && gmin[g] == m) {
                    bool f2 = false;
#pragma unroll
                    for (int k = 0; k < 8; k++) {
                        if (!f2 && u[8 * g + k] == m) {
                            u[8 * g + k] = 0xffffffffu;
                            s_win[j] = p0 + 8 * g + k;
                            f2 = true;
                        }
                    }
                    u32 nm = u[8 * g];
#pragma unroll
                    for (int k = 1; k < 8; k++) nm = min(nm, u[8 * g + k]);
                    gmin[g] = nm;
                    found = true;
                }
            }
            tmin = min(min(gmin[0], gmin[1]), min(gmin[2], gmin[3]));
        }
    }

    __syncthreads();
    if (t < NB) {
        const int win = s_win[t];
        const float x = base[win], y = base[NN + win], z = base[2 * NN + win];
        const size_t r = (size_t)b * 1536 + (size_t)q * NB + t;
        float* o1 = out + r * 3;
        o1[0] = x; o1[1] = y; o1[2] = z;
        float* o2 = out + (r + 512) * 3;
        o2[0] = x; o2[1] = y; o2[2] = z;
    }
}

// ============================================================================
// Launch: side stream runs the anchor pipeline (fps50 -> count -> top4 ->
// knn) overlapped with the full 512-iteration FPS on the main stream.
// Disjoint out regions; no shared state.  Streams/events created fresh per
// call (host-side objects only; not destroyed to keep the capture valid).
// ============================================================================
extern "C" void kernel_launch(void* const* d_in, const int* in_sizes, int n_in,
                              void* d_out, int out_size)
{
    const float* pts = (const float*)d_in[0];
    float* out = (float*)d_out;

    cudaFuncSetAttribute(fps_kernel<NANC, false>,
                         cudaFuncAttributeMaxDynamicSharedMemorySize, FPS_SMEM);
    cudaFuncSetAttribute(fps_kernel<NFPS, true>,
                         cudaFuncAttributeMaxDynamicSharedMemorySize, FPS_SMEM);

    cudaStream_t s2;
    cudaStreamCreateWithFlags(&s2, cudaStreamNonBlocking);
    cudaEvent_t e1, e2;
    cudaEventCreateWithFlags(&e1, cudaEventDisableTiming);
    cudaEventCreateWithFlags(&e2, cudaEventDisableTiming);

    cudaEventRecord(e1, 0);             // fork
    cudaStreamWaitEvent(s2, e1, 0);

    fps_kernel<NANC, false><<<dim3(CSZ, BB), FT, FPS_SMEM, s2>>>(pts, out);
    count_kernel<<<dim3(NREG, BB), 256, 0, s2>>>(pts);
    top4_kernel<<<BB, 32, 0, s2>>>();
    knn_kernel<<<dim3(TOPK, BB), KT, 0, s2>>>(pts, out);
    cudaEventRecord(e2, s2);

    fps_kernel<NFPS, true><<<dim3(CSZ, BB), FT, FPS_SMEM>>>(pts, out);

    cudaStreamWaitEvent(0, e2, 0);      // join
}